// round 14
// baseline (speedup 1.0000x reference)
#include <cuda_runtime.h>
#include <cstdint>

#define B_   2
#define H_   56
#define W_   56
#define C_   256
#define NH_  8
#define HD_  32
#define KW_  7
#define NPIX (B_*H_*W_)          // 6272
#define ATTN_ELEMS (B_*NH_*H_*W_*KW_*KW_)   // 2458624
#define OUT_ELEMS  (NPIX*C_)                // 1605632
#define SCALE 0.17677669529663687f          // 1/sqrt(32)

// ---- scratch (no allocations allowed) ----
__device__ float    g_q [NPIX*C_];
__device__ float    g_k [NPIX*C_];
__device__ float    g_v [NPIX*C_];
__device__ float    g_attn_dummy[ATTN_ELEMS];
// fragment-layout tf32 scratch
__device__ unsigned g_xf  [NPIX*C_];      // x,   A-layout
__device__ unsigned g_aof [NPIX*C_];      // attn out, A-layout (written by attn)
__device__ unsigned g_bqkv[768*C_];       // concat(w_qk, w_v), B-layout
__device__ unsigned g_bproj[C_*C_];       // w_proj, B-layout

// ======================================================================
// Fragment layouts (m16n8k8 tf32 register images), K/8 = 32 blocks:
//  A: block b=(m/16)*32+(k/8), 128 uints: off = ((m&7)*4+(k&3))*4
//       + ((m>>3)&1) + 2*((k>>2)&1)
//  B: block b=(n/8)*32+(k/8),   64 uints: off = ((n&7)*4+(k&3))*2 + ((k>>2)&1)
// ======================================================================

__device__ __forceinline__ unsigned f2tf(float f) {
    unsigned u; asm("cvt.rna.tf32.f32 %0, %1;" : "=r"(u) : "f"(f)); return u;
}

__device__ __forceinline__ void mma_tf32(float c[4], const uint4& a, const uint2& b) {
    asm volatile(
        "mma.sync.aligned.m16n8k8.row.col.f32.tf32.tf32.f32 "
        "{%0,%1,%2,%3}, {%4,%5,%6,%7}, {%8,%9}, {%0,%1,%2,%3};"
        : "+f"(c[0]), "+f"(c[1]), "+f"(c[2]), "+f"(c[3])
        : "r"(a.x), "r"(a.y), "r"(a.z), "r"(a.w), "r"(b.x), "r"(b.y));
}

// ---- prep: convert f32 row-major [rows,256] into fragment-layout tf32 ----
__global__ void __launch_bounds__(256) prep_a(
    const float* __restrict__ src, unsigned* __restrict__ dst)
{
    const int o      = blockIdx.x * 256 + threadIdx.x;   // one output uint
    const int within = o & 127;
    const int blk    = o >> 7;
    const int lane   = within >> 2;
    const int reg    = within & 3;
    const int kblk   = blk & 31;
    const int mblk   = blk >> 5;
    const int m = mblk * 16 + ((reg & 1) << 3) + (lane >> 2);
    const int k = kblk * 8  + ((reg >> 1) << 2) + (lane & 3);
    dst[o] = f2tf(src[m * C_ + k]);
}

__global__ void __launch_bounds__(256) prep_b(
    const float* __restrict__ src, unsigned* __restrict__ dst)
{
    const int o      = blockIdx.x * 256 + threadIdx.x;
    const int within = o & 63;
    const int blk    = o >> 6;
    const int lane   = within >> 1;
    const int reg    = within & 1;
    const int kblk   = blk & 31;
    const int nblk   = blk >> 5;
    const int n = nblk * 8 + (lane >> 2);
    const int k = kblk * 8 + (reg << 2) + (lane & 3);
    dst[o] = f2tf(src[n * C_ + k]);
}

// ======================================================================
// TF32 GEMM: CTA tile 128x64, BK=16, 256 threads (8 warps of 32x32).
// Stagers are pure coalesced copies of pre-converted fragment data:
//   A: warp w = mblk w; 2x(LDG.128 + STS.128)/thread/tile
//   B: warp w = nblk w; 1x(LDG.128 + STS.128)/thread/tile
// Smem (double buffered): A [mblk8][kblk2][lane][4], B [nblk8][kblk2][lane][2]
// ======================================================================
#define BM 128
#define BN 64
#define NKT 16               // 256/16 k-tiles
#define A_STRIDE 2048        // uints per A buffer
#define B_STRIDE 1024        // uints per B buffer

__device__ __forceinline__ void mma_mainloop(
    const uint4* __restrict__ A4, const uint4* __restrict__ B4,
    int mb0, int nb0, float acc[2][4][4],
    unsigned* AsS, unsigned* BsS)
{
    const int tid    = threadIdx.x;
    const int lane   = tid & 31;
    const int warp   = tid >> 5;
    const int warp_m = warp & 3;
    const int warp_n = warp >> 2;

    const int kbsel = lane >> 4;    // B: which kblk this half-warp copies
    const int l15   = lane & 15;

    // global bases (uint4 indices); per tile t add t*64 (A) / t*32 (B)
    const uint4* Ab = A4 + ((size_t)(mb0 + warp) * 32) * 32 + lane;
    const uint4* Bb = B4 + ((size_t)(nb0 + warp) * 32 + kbsel) * 16 + l15;

    uint4 la0, la1, lb;

    la0 = Ab[0]; la1 = Ab[32]; lb = Bb[0];
    ((uint4*)AsS)[(warp * 2 + 0) * 32 + lane] = la0;
    ((uint4*)AsS)[(warp * 2 + 1) * 32 + lane] = la1;
    ((uint4*)BsS)[(warp * 2 + kbsel) * 16 + l15] = lb;
    __syncthreads();

    for (int t = 0; t < NKT; t++) {
        const int buf = t & 1;
        if (t + 1 < NKT) {
            la0 = Ab[(t + 1) * 64];
            la1 = Ab[(t + 1) * 64 + 32];
            lb  = Bb[(t + 1) * 32];
        }

        const uint4* As4 = (const uint4*)(AsS + buf * A_STRIDE);
        const uint2* Bs2 = (const uint2*)(BsS + buf * B_STRIDE);

        #pragma unroll
        for (int kb = 0; kb < 2; kb++) {
            uint4 af0 = As4[((warp_m * 2 + 0) * 2 + kb) * 32 + lane];
            uint4 af1 = As4[((warp_m * 2 + 1) * 2 + kb) * 32 + lane];
            uint2 bf0 = Bs2[((warp_n * 4 + 0) * 2 + kb) * 32 + lane];
            uint2 bf1 = Bs2[((warp_n * 4 + 1) * 2 + kb) * 32 + lane];
            uint2 bf2 = Bs2[((warp_n * 4 + 2) * 2 + kb) * 32 + lane];
            uint2 bf3 = Bs2[((warp_n * 4 + 3) * 2 + kb) * 32 + lane];
            mma_tf32(acc[0][0], af0, bf0);
            mma_tf32(acc[0][1], af0, bf1);
            mma_tf32(acc[0][2], af0, bf2);
            mma_tf32(acc[0][3], af0, bf3);
            mma_tf32(acc[1][0], af1, bf0);
            mma_tf32(acc[1][1], af1, bf1);
            mma_tf32(acc[1][2], af1, bf2);
            mma_tf32(acc[1][3], af1, bf3);
        }

        if (t + 1 < NKT) {
            uint4* Asw = (uint4*)(AsS + (buf ^ 1) * A_STRIDE);
            uint4* Bsw = (uint4*)(BsS + (buf ^ 1) * B_STRIDE);
            Asw[(warp * 2 + 0) * 32 + lane] = la0;
            Asw[(warp * 2 + 1) * 32 + lane] = la1;
            Bsw[(warp * 2 + kbsel) * 16 + l15] = lb;
            __syncthreads();
        }
    }
}

// ======================================================================
// GEMM 1: fused QKV.  j < 256 -> q (scaled), 256..511 -> k, 512..767 -> v
// ======================================================================
__global__ void __launch_bounds__(256) gemm_qkv()
{
    __shared__ unsigned As[2 * A_STRIDE];
    __shared__ unsigned Bs[2 * B_STRIDE];

    const int m0 = blockIdx.x * BM;
    const int j0 = blockIdx.y * BN;

    float acc[2][4][4] = {};
    mma_mainloop((const uint4*)g_xf, (const uint4*)g_bqkv,
                 m0 >> 4, j0 >> 3, acc, As, Bs);

    float* dst; int coff; float sc;
    if (j0 < 256)      { dst = g_q; coff = j0;       sc = SCALE; }
    else if (j0 < 512) { dst = g_k; coff = j0 - 256; sc = 1.0f;  }
    else               { dst = g_v; coff = j0 - 512; sc = 1.0f;  }

    const int lane = threadIdx.x & 31;
    const int warp = threadIdx.x >> 5;
    const int g  = lane >> 2;
    const int t4 = lane & 3;

    #pragma unroll
    for (int i = 0; i < 2; i++) {
        #pragma unroll
        for (int j = 0; j < 4; j++) {
            const int row = m0 + (warp & 3) * 32 + i * 16 + g;
            const int col = coff + (warp >> 2) * 32 + j * 8 + t4 * 2;
            *(float2*)&dst[(size_t)row * C_ + col] =
                make_float2(acc[i][j][0] * sc, acc[i][j][1] * sc);
            *(float2*)&dst[(size_t)(row + 8) * C_ + col] =
                make_float2(acc[i][j][2] * sc, acc[i][j][3] * sc);
        }
    }
}

// ======================================================================
// GEMM 2: projection.  out[n, j] = sum_k ao[n,k] * w_proj[j,k] + b[j]
// ======================================================================
__global__ void __launch_bounds__(256) gemm_proj(
    const float* __restrict__ bias, float* __restrict__ out)
{
    __shared__ unsigned As[2 * A_STRIDE];
    __shared__ unsigned Bs[2 * B_STRIDE];

    const int m0 = blockIdx.x * BM;
    const int j0 = blockIdx.y * BN;

    float acc[2][4][4] = {};
    mma_mainloop((const uint4*)g_aof, (const uint4*)g_bproj,
                 m0 >> 4, j0 >> 3, acc, As, Bs);

    const int lane = threadIdx.x & 31;
    const int warp = threadIdx.x >> 5;
    const int g  = lane >> 2;
    const int t4 = lane & 3;

    #pragma unroll
    for (int i = 0; i < 2; i++) {
        #pragma unroll
        for (int j = 0; j < 4; j++) {
            const int row = m0 + (warp & 3) * 32 + i * 16 + g;
            const int col = j0 + (warp >> 2) * 32 + j * 8 + t4 * 2;
            const float2 bv = *(const float2*)&bias[col];
            *(float2*)&out[(size_t)row * C_ + col] =
                make_float2(acc[i][j][0] + bv.x, acc[i][j][1] + bv.y);
            *(float2*)&out[(size_t)(row + 8) * C_ + col] =
                make_float2(acc[i][j][2] + bv.x, acc[i][j][3] + bv.y);
        }
    }
}

// ======================================================================
// Attention (tiled): one CTA = (batch, head, 8x4 pixel tile).
// Output now stored tf32-converted in A-fragment layout (g_aof) so
// gemm_proj's stager is a pure copy.
// ======================================================================
#define TR 8
#define TC 4
#define HR 14
#define HC 10
#define KSTR 33

__global__ void __launch_bounds__(256) attn_tile(float* __restrict__ attn_ext, int ext)
{
    __shared__ float ks[HR*HC*KSTR];
    __shared__ float vs[HR*HC*32];

    const int c0 = blockIdx.x * TC;
    const int r0 = blockIdx.y * TR;
    const int bh = blockIdx.z;
    const int h  = bh & 7;
    const int b  = bh >> 3;

    const int rb = max(r0 - 3, 0);
    const int rn = min(r0 + TR + 2, H_ - 1) - rb + 1;
    const int cb = max(c0 - 3, 0);
    const int cn = min(c0 + TC + 2, W_ - 1) - cb + 1;

    const int warp = threadIdx.x >> 5;
    const int lane = threadIdx.x & 31;

    float* ap = ext ? attn_ext : g_attn_dummy;

    const int area = rn * cn;
    for (int p = warp; p < area; p += 8) {
        const int plr = p / cn;
        const int plc = p - plr * cn;
        const int pix = (b * H_ + rb + plr) * W_ + cb + plc;
        const size_t ga = (size_t)pix * C_ + h * HD_ + lane;
        const int sp = plr * HC + plc;
        ks[sp * KSTR + lane] = g_k[ga];
        vs[sp * 32   + lane] = g_v[ga];
    }
    __syncthreads();

    const int i   = r0 + warp;
    const int shl = min(max(i - 3, 0), H_ - KW_) - rb;
    const int o0 = (shl + lane / 7) * HC + lane % 7;
    const int t1 = (lane < 17) ? lane + 32 : 32;
    const int o1 = (shl + t1 / 7) * HC + t1 % 7;

    // fragment-store constants: k = h*32 + lane (per-lane channel)
    const int kch   = h * HD_ + lane;
    const int kblk  = kch >> 3;
    const int fragk = (kch & 3) * 4 + (((kch >> 2) & 1) << 1);  // lane-part + reg-bit1

    for (int jj = 0; jj < TC; jj++) {
        const int j   = c0 + jj;
        const int swl = min(max(j - 3, 0), W_ - KW_) - cb;
        const int pix = (b * H_ + i) * W_ + j;
        const int p0  = o0 + swl;
        const int p1  = o1 + swl;

        const float q = g_q[(size_t)pix * C_ + h * HD_ + lane];

        float l0 = 0.0f, l1 = 0.0f;
        #pragma unroll
        for (int d = 0; d < 32; d++) {
            const float qd = __shfl_sync(0xffffffffu, q, d);
            l0 = fmaf(qd, ks[p0 * KSTR + d], l0);
            l1 = fmaf(qd, ks[p1 * KSTR + d], l1);
        }
        if (lane >= 17) l1 = -1e30f;

        float m = fmaxf(l0, l1);
        #pragma unroll
        for (int o = 16; o > 0; o >>= 1)
            m = fmaxf(m, __shfl_xor_sync(0xffffffffu, m, o));
        const float e0 = __expf(l0 - m);
        const float e1 = (lane < 17) ? __expf(l1 - m) : 0.0f;
        float s = e0 + e1;
        #pragma unroll
        for (int o = 16; o > 0; o >>= 1)
            s += __shfl_xor_sync(0xffffffffu, s, o);
        const float inv = 1.0f / s;

        const size_t abase = (size_t)(((b * NH_ + h) * H_ + i) * W_ + j) * 49;
        ap[abase + lane] = e0 * inv;
        if (lane < 17) ap[abase + 32 + lane] = e1 * inv;

        const int pb = shl * HC + swl;
        float acc = 0.0f;
        #pragma unroll
        for (int t = 0; t < 49; t++) {
            const float a = (t < 32) ? __shfl_sync(0xffffffffu, e0, t)
                                     : __shfl_sync(0xffffffffu, e1, t - 32);
            acc = fmaf(a, vs[(pb + (t / 7) * HC + (t % 7)) * 32 + lane], acc);
        }

        // store tf32 in A-fragment layout: m = pix, k = kch
        const int blk = (pix >> 4) * 32 + kblk;
        const int off = (pix & 7) * 16 + ((pix >> 3) & 1) + fragk;
        g_aof[blk * 128 + off] = f2tf(acc * inv);
    }
}

// ======================================================================
extern "C" void kernel_launch(void* const* d_in, const int* in_sizes, int n_in,
                              void* d_out, int out_size)
{
    const float* x      = (const float*)d_in[0];
    const float* w_qk   = (const float*)d_in[1];
    const float* w_v    = (const float*)d_in[2];
    const float* w_proj = (const float*)d_in[3];
    const float* b_proj = (const float*)d_in[4];
    float* out = (float*)d_out;

    const int ext = (out_size >= OUT_ELEMS + ATTN_ELEMS) ? 1 : 0;
    float* attn_ptr = out + OUT_ELEMS;   // used only when ext==1

    unsigned* xf;  cudaGetSymbolAddress((void**)&xf,  g_xf);
    unsigned* bq;  cudaGetSymbolAddress((void**)&bq,  g_bqkv);
    unsigned* bp;  cudaGetSymbolAddress((void**)&bp,  g_bproj);

    // prep: fragment-layout tf32 conversion (done once per launch)
    prep_a<<<NPIX * C_ / 256, 256>>>(x, xf);
    prep_b<<<512 * C_ / 256, 256>>>(w_qk, bq);
    prep_b<<<256 * C_ / 256, 256>>>(w_v,  bq + 64 * 2048);  // nblk 64.. of concat
    prep_b<<<256 * C_ / 256, 256>>>(w_proj, bp);

    gemm_qkv <<<dim3(NPIX / BM, 768 / BN), 256>>>();
    attn_tile<<<dim3(W_ / TC, H_ / TR, B_ * NH_), 256>>>(attn_ptr, ext);
    gemm_proj<<<dim3(NPIX / BM, C_ / BN), 256>>>(b_proj, out);
}

// round 15
// speedup vs baseline: 1.4550x; 1.4550x over previous
#include <cuda_runtime.h>
#include <cstdint>

#define B_   2
#define H_   56
#define W_   56
#define C_   256
#define NH_  8
#define HD_  32
#define KW_  7
#define NPIX (B_*H_*W_)          // 6272
#define ATTN_ELEMS (B_*NH_*H_*W_*KW_*KW_)   // 2458624
#define OUT_ELEMS  (NPIX*C_)                // 1605632
#define SCALE 0.17677669529663687f          // 1/sqrt(32)

// ---- scratch (no allocations allowed) ----
__device__ float g_q [NPIX*C_];
__device__ float g_k [NPIX*C_];
__device__ float g_v [NPIX*C_];
__device__ float g_ao[NPIX*C_];
__device__ float g_attn_dummy[ATTN_ELEMS];

// ======================================================================
// TF32 tensor-core GEMM core (mma.sync.m16n8k8) — identical to R13.
// CTA tile 128x64, BK=16, 256 threads (8 warps, each 32x32 = 2x4 m16n8k8).
// A staged via cross-lane 4x4 quad transpose -> one conflict-free STS.128.
// ======================================================================
#define BM 128
#define BN 64
#define BKT 16
#define NKT (C_ / BKT)       // 16 k-tiles
#define A_STRIDE 2048        // uints per A buffer (8*2*32*4)
#define B_STRIDE 1024        // uints per B buffer (8*2*32*2)

__device__ __forceinline__ unsigned f2tf(float f) {
    unsigned u; asm("cvt.rna.tf32.f32 %0, %1;" : "=r"(u) : "f"(f)); return u;
}

__device__ __forceinline__ void mma_tf32(float c[4], const uint4& a, const uint2& b) {
    asm volatile(
        "mma.sync.aligned.m16n8k8.row.col.f32.tf32.tf32.f32 "
        "{%0,%1,%2,%3}, {%4,%5,%6,%7}, {%8,%9}, {%0,%1,%2,%3};"
        : "+f"(c[0]), "+f"(c[1]), "+f"(c[2]), "+f"(c[3])
        : "r"(a.x), "r"(a.y), "r"(a.z), "r"(a.w), "r"(b.x), "r"(b.y));
}

// 4x4 transpose across a lane quad (2-stage butterfly, static indices).
__device__ __forceinline__ void quad_transpose(
    unsigned& x0, unsigned& x1, unsigned& x2, unsigned& x3, int q)
{
    unsigned t;
    t = (q & 1) ? x0 : x1;  t = __shfl_xor_sync(0xffffffffu, t, 1);
    if (q & 1) x0 = t; else x1 = t;
    t = (q & 1) ? x2 : x3;  t = __shfl_xor_sync(0xffffffffu, t, 1);
    if (q & 1) x2 = t; else x3 = t;
    t = (q & 2) ? x0 : x2;  t = __shfl_xor_sync(0xffffffffu, t, 2);
    if (q & 2) x0 = t; else x2 = t;
    t = (q & 2) ? x1 : x3;  t = __shfl_xor_sync(0xffffffffu, t, 2);
    if (q & 2) x1 = t; else x3 = t;
}

// scatter one B float4 (row bn, tile-k kk..kk+3) -- 2-way conflicts, OK
__device__ __forceinline__ void sts_b(unsigned* Bs, int bn, int kk, float4 v) {
    const int nblk = bn >> 3;
    const int kblk = kk >> 3;
    const int reg  = (kk >> 2) & 1;
    const int base = ((nblk * 2 + kblk) * 32 + (bn & 7) * 4) * 2 + reg;
    Bs[base]     = f2tf(v.x);
    Bs[base + 2] = f2tf(v.y);
    Bs[base + 4] = f2tf(v.z);
    Bs[base + 6] = f2tf(v.w);
}

// stage one BK=16 tile: A via quad transpose + STS.128, B via scatter
__device__ __forceinline__ void stage_tile(
    unsigned* Asw, unsigned* Bsw,
    float4 la0, float4 la1, float4 lb,
    int warp, int lane, int q, int bn, int bk)
{
    #pragma unroll
    for (int kb = 0; kb < 2; kb++) {
        float4 v = kb ? la1 : la0;
        unsigned x0 = f2tf(v.x), x1 = f2tf(v.y), x2 = f2tf(v.z), x3 = f2tf(v.w);
        quad_transpose(x0, x1, x2, x3, q);
        ((uint4*)Asw)[(warp * 2 + kb) * 32 + lane] = make_uint4(x0, x1, x2, x3);
    }
    sts_b(Bsw, bn, bk, lb);
}

__device__ __forceinline__ void mma_mainloop(
    const float* __restrict__ A, const float* __restrict__ Wm,
    int m0, float acc[2][4][4],
    unsigned* AsS, unsigned* BsS)    // [2][A_STRIDE], [2][B_STRIDE]
{
    const int tid    = threadIdx.x;
    const int lane   = tid & 31;
    const int warp   = tid >> 5;
    const int warp_m = warp & 3;      // 4 m-groups of 32 rows
    const int warp_n = warp >> 2;     // 2 n-groups of 32 cols

    const int g    = lane >> 2;
    const int q    = lane & 3;
    const int arow = warp * 16 + g + 8 * (q & 1);
    const int akq4 = ((lane >> 1) & 1) * 4;      // (q>>1)*4

    const int bn  = tid >> 2;               // B row 0..63
    const int bk  = (tid & 3) * 4;          // B k-offset

    const float* ArowP = A  + (size_t)(m0 + arow) * C_;
    const float* Brow  = Wm + (size_t)bn * C_;

    float4 la0, la1, lb;

    la0 = *(const float4*)(ArowP + akq4);
    la1 = *(const float4*)(ArowP + 8 + akq4);
    lb  = *(const float4*)(Brow + bk);
    stage_tile(AsS, BsS, la0, la1, lb, warp, lane, q, bn, bk);
    __syncthreads();

    for (int t = 0; t < NKT; t++) {
        const int buf = t & 1;
        if (t + 1 < NKT) {
            const int k0 = (t + 1) * BKT;
            la0 = *(const float4*)(ArowP + k0 + akq4);
            la1 = *(const float4*)(ArowP + k0 + 8 + akq4);
            lb  = *(const float4*)(Brow + k0 + bk);
        }

        const uint4* As4 = (const uint4*)(AsS + buf * A_STRIDE);
        const uint2* Bs2 = (const uint2*)(BsS + buf * B_STRIDE);

        #pragma unroll
        for (int kb = 0; kb < 2; kb++) {
            uint4 af0 = As4[((warp_m * 2 + 0) * 2 + kb) * 32 + lane];
            uint4 af1 = As4[((warp_m * 2 + 1) * 2 + kb) * 32 + lane];
            uint2 bf0 = Bs2[((warp_n * 4 + 0) * 2 + kb) * 32 + lane];
            uint2 bf1 = Bs2[((warp_n * 4 + 1) * 2 + kb) * 32 + lane];
            uint2 bf2 = Bs2[((warp_n * 4 + 2) * 2 + kb) * 32 + lane];
            uint2 bf3 = Bs2[((warp_n * 4 + 3) * 2 + kb) * 32 + lane];
            mma_tf32(acc[0][0], af0, bf0);
            mma_tf32(acc[0][1], af0, bf1);
            mma_tf32(acc[0][2], af0, bf2);
            mma_tf32(acc[0][3], af0, bf3);
            mma_tf32(acc[1][0], af1, bf0);
            mma_tf32(acc[1][1], af1, bf1);
            mma_tf32(acc[1][2], af1, bf2);
            mma_tf32(acc[1][3], af1, bf3);
        }

        if (t + 1 < NKT) {
            stage_tile(AsS + (buf ^ 1) * A_STRIDE, BsS + (buf ^ 1) * B_STRIDE,
                       la0, la1, lb, warp, lane, q, bn, bk);
            __syncthreads();
        }
    }
}

// ======================================================================
// GEMM 1: fused QKV.  j < 256 -> q (scaled), 256..511 -> k, 512..767 -> v
// ======================================================================
__global__ void __launch_bounds__(256) gemm_qkv(
    const float* __restrict__ x,
    const float* __restrict__ w_qk,
    const float* __restrict__ w_v)
{
    __shared__ unsigned As[2 * A_STRIDE];
    __shared__ unsigned Bs[2 * B_STRIDE];

    const int m0 = blockIdx.x * BM;
    const int j0 = blockIdx.y * BN;
    const float* Wmat = (j0 < 512) ? (w_qk + (size_t)j0 * C_)
                                   : (w_v  + (size_t)(j0 - 512) * C_);

    float acc[2][4][4] = {};
    mma_mainloop(x, Wmat, m0, acc, As, Bs);

    float* dst; int coff; float sc;
    if (j0 < 256)      { dst = g_q; coff = j0;       sc = SCALE; }
    else if (j0 < 512) { dst = g_k; coff = j0 - 256; sc = 1.0f;  }
    else               { dst = g_v; coff = j0 - 512; sc = 1.0f;  }

    const int lane = threadIdx.x & 31;
    const int warp = threadIdx.x >> 5;
    const int g  = lane >> 2;
    const int t4 = lane & 3;

    #pragma unroll
    for (int i = 0; i < 2; i++) {
        #pragma unroll
        for (int j = 0; j < 4; j++) {
            const int row = m0 + (warp & 3) * 32 + i * 16 + g;
            const int col = coff + (warp >> 2) * 32 + j * 8 + t4 * 2;
            *(float2*)&dst[(size_t)row * C_ + col] =
                make_float2(acc[i][j][0] * sc, acc[i][j][1] * sc);
            *(float2*)&dst[(size_t)(row + 8) * C_ + col] =
                make_float2(acc[i][j][2] * sc, acc[i][j][3] * sc);
        }
    }
}

// ======================================================================
// GEMM 2: projection.  out[n, j] = sum_k g_ao[n,k] * w_proj[j,k] + b[j]
// ======================================================================
__global__ void __launch_bounds__(256) gemm_proj(
    const float* __restrict__ Wp,
    const float* __restrict__ bias,
    float* __restrict__ out)
{
    __shared__ unsigned As[2 * A_STRIDE];
    __shared__ unsigned Bs[2 * B_STRIDE];

    const int m0 = blockIdx.x * BM;
    const int j0 = blockIdx.y * BN;

    float acc[2][4][4] = {};
    mma_mainloop(g_ao, Wp + (size_t)j0 * C_, m0, acc, As, Bs);

    const int lane = threadIdx.x & 31;
    const int warp = threadIdx.x >> 5;
    const int g  = lane >> 2;
    const int t4 = lane & 3;

    #pragma unroll
    for (int i = 0; i < 2; i++) {
        #pragma unroll
        for (int j = 0; j < 4; j++) {
            const int row = m0 + (warp & 3) * 32 + i * 16 + g;
            const int col = j0 + (warp >> 2) * 32 + j * 8 + t4 * 2;
            const float2 bv = *(const float2*)&bias[col];
            *(float2*)&out[(size_t)row * C_ + col] =
                make_float2(acc[i][j][0] + bv.x, acc[i][j][1] + bv.y);
            *(float2*)&out[(size_t)(row + 8) * C_ + col] =
                make_float2(acc[i][j][2] + bv.x, acc[i][j][3] + bv.y);
        }
    }
}

// ======================================================================
// Attention (tiled): one CTA = (batch, head, 8x4 pixel tile).
// R15: QK vectorized — q tile staged in smem, K stride padded to 36 words
// so each neighbor row is 16B-aligned; inner loop = 8x(3 LDS.128 + 8 FMA)
// instead of 32x(shfl + 2 LDS.32 + 2 FMA).
// ======================================================================
#define TR 8
#define TC 4
#define HR 14
#define HC 10
#define KSTR 36              // padded: 16B-aligned rows, balanced quad residues

__global__ void __launch_bounds__(256) attn_tile(float* __restrict__ attn_ext, int ext)
{
    __shared__ __align__(16) float ks[HR*HC*KSTR];   // 20160 B
    __shared__ __align__(16) float vs[HR*HC*32];     // 17920 B
    __shared__ __align__(16) float qs[TR*TC*32];     //  4096 B

    const int c0 = blockIdx.x * TC;
    const int r0 = blockIdx.y * TR;
    const int bh = blockIdx.z;
    const int h  = bh & 7;
    const int b  = bh >> 3;

    const int rb = max(r0 - 3, 0);
    const int rn = min(r0 + TR + 2, H_ - 1) - rb + 1;
    const int cb = max(c0 - 3, 0);
    const int cn = min(c0 + TC + 2, W_ - 1) - cb + 1;

    const int warp = threadIdx.x >> 5;
    const int lane = threadIdx.x & 31;

    float* ap = ext ? attn_ext : g_attn_dummy;

    // ---- fill K/V halo ----
    const int area = rn * cn;
    for (int p = warp; p < area; p += 8) {
        const int plr = p / cn;
        const int plc = p - plr * cn;
        const int pix = (b * H_ + rb + plr) * W_ + cb + plc;
        const size_t ga = (size_t)pix * C_ + h * HD_ + lane;
        const int sp = plr * HC + plc;
        ks[sp * KSTR + lane] = g_k[ga];
        vs[sp * 32   + lane] = g_v[ga];
    }
    // ---- fill q tile (warp w -> row r0+w, 4 cols) ----
    {
        const int i = r0 + warp;
        #pragma unroll
        for (int jj = 0; jj < TC; jj++) {
            const int pix = (b * H_ + i) * W_ + c0 + jj;
            qs[(warp * TC + jj) * 32 + lane] = g_q[(size_t)pix * C_ + h * HD_ + lane];
        }
    }
    __syncthreads();

    const int i   = r0 + warp;
    const int shl = min(max(i - 3, 0), H_ - KW_) - rb;
    const int o0 = (shl + lane / 7) * HC + lane % 7;
    const int t1 = (lane < 17) ? lane + 32 : 32;
    const int o1 = (shl + t1 / 7) * HC + t1 % 7;

    for (int jj = 0; jj < TC; jj++) {
        const int j   = c0 + jj;
        const int swl = min(max(j - 3, 0), W_ - KW_) - cb;
        const int pix = (b * H_ + i) * W_ + j;
        const int p0  = o0 + swl;
        const int p1  = o1 + swl;

        // ---- QK: 2 logits per lane, float4 over d ----
        const float4* qrow = (const float4*)&qs[(warp * TC + jj) * 32];
        const float4* k0p  = (const float4*)&ks[p0 * KSTR];
        const float4* k1p  = (const float4*)&ks[p1 * KSTR];
        float l0 = 0.0f, l1 = 0.0f;
        #pragma unroll
        for (int dq = 0; dq < 8; dq++) {
            const float4 qd = qrow[dq];      // broadcast
            const float4 k0 = k0p[dq];
            const float4 k1 = k1p[dq];
            l0 = fmaf(qd.x, k0.x, fmaf(qd.y, k0.y, fmaf(qd.z, k0.z, fmaf(qd.w, k0.w, l0))));
            l1 = fmaf(qd.x, k1.x, fmaf(qd.y, k1.y, fmaf(qd.z, k1.z, fmaf(qd.w, k1.w, l1))));
        }
        if (lane >= 17) l1 = -1e30f;

        // ---- softmax over 49 ----
        float m = fmaxf(l0, l1);
        #pragma unroll
        for (int o = 16; o > 0; o >>= 1)
            m = fmaxf(m, __shfl_xor_sync(0xffffffffu, m, o));
        const float e0 = __expf(l0 - m);
        const float e1 = (lane < 17) ? __expf(l1 - m) : 0.0f;
        float s = e0 + e1;
        #pragma unroll
        for (int o = 16; o > 0; o >>= 1)
            s += __shfl_xor_sync(0xffffffffu, s, o);
        const float inv = 1.0f / s;

        const size_t abase = (size_t)(((b * NH_ + h) * H_ + i) * W_ + j) * 49;
        ap[abase + lane] = e0 * inv;
        if (lane < 17) ap[abase + 32 + lane] = e1 * inv;

        // ---- AV: lane = dim, broadcast weights via shfl ----
        const int pb = shl * HC + swl;
        float acc = 0.0f;
        #pragma unroll
        for (int t = 0; t < 49; t++) {
            const float a = (t < 32) ? __shfl_sync(0xffffffffu, e0, t)
                                     : __shfl_sync(0xffffffffu, e1, t - 32);
            acc = fmaf(a, vs[(pb + (t / 7) * HC + (t % 7)) * 32 + lane], acc);
        }
        g_ao[(size_t)pix * C_ + h * HD_ + lane] = acc * inv;
    }
}

// ======================================================================
extern "C" void kernel_launch(void* const* d_in, const int* in_sizes, int n_in,
                              void* d_out, int out_size)
{
    const float* x      = (const float*)d_in[0];
    const float* w_qk   = (const float*)d_in[1];
    const float* w_v    = (const float*)d_in[2];
    const float* w_proj = (const float*)d_in[3];
    const float* b_proj = (const float*)d_in[4];
    float* out = (float*)d_out;

    const int ext = (out_size >= OUT_ELEMS + ATTN_ELEMS) ? 1 : 0;
    float* attn_ptr = out + OUT_ELEMS;   // used only when ext==1

    gemm_qkv <<<dim3(NPIX / BM, 768 / BN), 256>>>(x, w_qk, w_v);
    attn_tile<<<dim3(W_ / TC, H_ / TR, B_ * NH_), 256>>>(attn_ptr, ext);
    gemm_proj<<<dim3(NPIX / BM, C_ / BN), 256>>>(w_proj, b_proj, out);
}

// round 16
// speedup vs baseline: 1.5330x; 1.0536x over previous
#include <cuda_runtime.h>
#include <cstdint>

#define B_   2
#define H_   56
#define W_   56
#define C_   256
#define NH_  8
#define HD_  32
#define KW_  7
#define NPIX (B_*H_*W_)          // 6272
#define ATTN_ELEMS (B_*NH_*H_*W_*KW_*KW_)   // 2458624
#define OUT_ELEMS  (NPIX*C_)                // 1605632
#define SCALE 0.17677669529663687f          // 1/sqrt(32)

// ---- scratch (no allocations allowed) ----
__device__ float    g_q [NPIX*C_];
__device__ float    g_k [NPIX*C_];
__device__ float    g_v [NPIX*C_];
__device__ float    g_ao[NPIX*C_];
__device__ float    g_attn_dummy[ATTN_ELEMS];
// fragment-layout tf32 scratch
__device__ unsigned g_xf   [NPIX*C_];     // x        -> A-fragment layout
__device__ unsigned g_aof  [NPIX*C_];     // attn out -> A-fragment layout
__device__ unsigned g_bqkv [768*C_];      // concat(w_qk, w_v) -> B-fragment layout
__device__ unsigned g_bproj[C_*C_];       // w_proj   -> B-fragment layout

// ======================================================================
// Fragment layouts (m16n8k8 tf32 register images), K/8 = 32 kblks:
//  A: block b = (m/16)*32 + (k/8); 128 uints; within-block:
//     lane=(m&7)*4+(k&3), reg = ((m>>3)&1) + 2*((k>>2)&1); uint = lane*4+reg
//  B: block b = (n/8)*32 + (k/8); 64 uints; within-block:
//     lane=(n&7)*4+(k&3), reg = (k>>2)&1;               uint = lane*2+reg
// ======================================================================

__device__ __forceinline__ unsigned f2tf(float f) {
    unsigned u; asm("cvt.rna.tf32.f32 %0, %1;" : "=r"(u) : "f"(f)); return u;
}

__device__ __forceinline__ void mma_tf32(float c[4], const uint4& a, const uint2& b) {
    asm volatile(
        "mma.sync.aligned.m16n8k8.row.col.f32.tf32.tf32.f32 "
        "{%0,%1,%2,%3}, {%4,%5,%6,%7}, {%8,%9}, {%0,%1,%2,%3};"
        : "+f"(c[0]), "+f"(c[1]), "+f"(c[2]), "+f"(c[3])
        : "r"(a.x), "r"(a.y), "r"(a.z), "r"(a.w), "r"(b.x), "r"(b.y));
}

// ======================================================================
// prep_afrag: [16 rows x 256] f32 block -> A-fragment tf32 (1024 uint4).
// Coalesced LDG.128 in, conflict-free smem (stride 260: bank=4g+t4 is a
// 0..31 permutation), coalesced STG.128 out.
// ======================================================================
#define SMP 260

__global__ void __launch_bounds__(256) prep_afrag(
    const float* __restrict__ src, unsigned* __restrict__ dst)
{
    __shared__ float sm[16 * SMP];
    const int t = threadIdx.x;
    const size_t grp = blockIdx.x;

    const float4* s4 = (const float4*)(src + grp * 16 * C_);
    #pragma unroll
    for (int i = 0; i < 4; i++) {
        const int f = t + 256 * i;           // float4 idx in 16x256 block
        const int row = f >> 6, c4 = f & 63;
        const float4 v = s4[f];
        float* d = &sm[row * SMP + c4 * 4];
        d[0] = v.x; d[1] = v.y; d[2] = v.z; d[3] = v.w;
    }
    __syncthreads();

    const int lane = t & 31;
    const int g = lane >> 2, t4 = lane & 3;
    uint4* o4 = (uint4*)dst + grp * 1024;
    #pragma unroll
    for (int i = 0; i < 4; i++) {
        const int u = t + 256 * i;           // uint4 idx in group; u&31 == lane
        const int kblk = u >> 5;
        const int k0 = kblk * 8 + t4;
        o4[u] = make_uint4(f2tf(sm[g * SMP + k0]),
                           f2tf(sm[(g + 8) * SMP + k0]),
                           f2tf(sm[g * SMP + k0 + 4]),
                           f2tf(sm[(g + 8) * SMP + k0 + 4]));
    }
}

// ======================================================================
// prep_ball: all three weight matrices -> B-fragment layout, one launch.
// grp 0..31: w_qk (512 rows); 32..47: w_v; 48..63: w_proj.
// ======================================================================
__global__ void __launch_bounds__(256) prep_ball(
    const float* __restrict__ w_qk, const float* __restrict__ w_v,
    const float* __restrict__ w_proj,
    unsigned* __restrict__ bqkv, unsigned* __restrict__ bproj)
{
    __shared__ float sm[16 * SMP];
    const int t = threadIdx.x;
    const int grp = blockIdx.x;

    const float* src; unsigned* dst;
    if (grp < 32)      { src = w_qk   + (size_t)grp * 16 * C_;        dst = bqkv  + (size_t)grp * 4096; }
    else if (grp < 48) { src = w_v    + (size_t)(grp - 32) * 16 * C_; dst = bqkv  + (size_t)grp * 4096; }
    else               { src = w_proj + (size_t)(grp - 48) * 16 * C_; dst = bproj + (size_t)(grp - 48) * 4096; }

    const float4* s4 = (const float4*)src;
    #pragma unroll
    for (int i = 0; i < 4; i++) {
        const int f = t + 256 * i;
        const int row = f >> 6, c4 = f & 63;
        const float4 v = s4[f];
        float* d = &sm[row * SMP + c4 * 4];
        d[0] = v.x; d[1] = v.y; d[2] = v.z; d[3] = v.w;
    }
    __syncthreads();

    uint4* o4 = (uint4*)dst;
    #pragma unroll
    for (int i = 0; i < 4; i++) {
        const int u = t + 256 * i;           // uint4 idx in group (0..1023)
        const int lb = u >> 4;               // local block: nbl*32 + kblk
        const int s  = u & 15;
        const int nbl  = lb >> 5, kblk = lb & 31;
        const int lf0 = 2 * s, lf1 = lf0 + 1;
        const int n0 = nbl * 8 + (lf0 >> 2), n1 = nbl * 8 + (lf1 >> 2);
        const int ka = kblk * 8 + (lf0 & 3), kb = kblk * 8 + (lf1 & 3);
        o4[u] = make_uint4(f2tf(sm[n0 * SMP + ka]),
                           f2tf(sm[n0 * SMP + ka + 4]),
                           f2tf(sm[n1 * SMP + kb]),
                           f2tf(sm[n1 * SMP + kb + 4]));
    }
}

// ======================================================================
// TF32 GEMM: CTA tile 128x64, BK=16, 256 threads (8 warps of 32x32).
// Stagers are pure coalesced copies of pre-converted fragment data.
// Smem (double buffered): A [mblk8][kb2][lane][4], B [nblk8][kb2][lane][2]
// ======================================================================
#define BM 128
#define BN 64
#define NKT 16
#define A_STRIDE 2048
#define B_STRIDE 1024

__device__ __forceinline__ void mma_mainloop(
    const uint4* __restrict__ A4, const uint4* __restrict__ B4,
    int mb0, int nb0, float acc[2][4][4],
    unsigned* AsS, unsigned* BsS)
{
    const int tid    = threadIdx.x;
    const int lane   = tid & 31;
    const int warp   = tid >> 5;
    const int warp_m = warp & 3;
    const int warp_n = warp >> 2;

    const int kbsel = lane >> 4;
    const int l15   = lane & 15;

    const uint4* Ab = A4 + ((size_t)(mb0 + warp) * 32) * 32 + lane;
    const uint4* Bb = B4 + ((size_t)(nb0 + warp) * 32 + kbsel) * 16 + l15;

    uint4 la0, la1, lb;

    la0 = Ab[0]; la1 = Ab[32]; lb = Bb[0];
    ((uint4*)AsS)[(warp * 2 + 0) * 32 + lane] = la0;
    ((uint4*)AsS)[(warp * 2 + 1) * 32 + lane] = la1;
    ((uint4*)BsS)[(warp * 2 + kbsel) * 16 + l15] = lb;
    __syncthreads();

    for (int t = 0; t < NKT; t++) {
        const int buf = t & 1;
        if (t + 1 < NKT) {
            la0 = Ab[(t + 1) * 64];
            la1 = Ab[(t + 1) * 64 + 32];
            lb  = Bb[(t + 1) * 32];
        }

        const uint4* As4 = (const uint4*)(AsS + buf * A_STRIDE);
        const uint2* Bs2 = (const uint2*)(BsS + buf * B_STRIDE);

        #pragma unroll
        for (int kb = 0; kb < 2; kb++) {
            uint4 af0 = As4[((warp_m * 2 + 0) * 2 + kb) * 32 + lane];
            uint4 af1 = As4[((warp_m * 2 + 1) * 2 + kb) * 32 + lane];
            uint2 bf0 = Bs2[((warp_n * 4 + 0) * 2 + kb) * 32 + lane];
            uint2 bf1 = Bs2[((warp_n * 4 + 1) * 2 + kb) * 32 + lane];
            uint2 bf2 = Bs2[((warp_n * 4 + 2) * 2 + kb) * 32 + lane];
            uint2 bf3 = Bs2[((warp_n * 4 + 3) * 2 + kb) * 32 + lane];
            mma_tf32(acc[0][0], af0, bf0);
            mma_tf32(acc[0][1], af0, bf1);
            mma_tf32(acc[0][2], af0, bf2);
            mma_tf32(acc[0][3], af0, bf3);
            mma_tf32(acc[1][0], af1, bf0);
            mma_tf32(acc[1][1], af1, bf1);
            mma_tf32(acc[1][2], af1, bf2);
            mma_tf32(acc[1][3], af1, bf3);
        }

        if (t + 1 < NKT) {
            uint4* Asw = (uint4*)(AsS + (buf ^ 1) * A_STRIDE);
            uint4* Bsw = (uint4*)(BsS + (buf ^ 1) * B_STRIDE);
            Asw[(warp * 2 + 0) * 32 + lane] = la0;
            Asw[(warp * 2 + 1) * 32 + lane] = la1;
            Bsw[(warp * 2 + kbsel) * 16 + l15] = lb;
            __syncthreads();
        }
    }
}

// ======================================================================
// GEMM 1: fused QKV.  j < 256 -> q (scaled), 256..511 -> k, 512..767 -> v
// ======================================================================
__global__ void __launch_bounds__(256) gemm_qkv()
{
    __shared__ unsigned As[2 * A_STRIDE];
    __shared__ unsigned Bs[2 * B_STRIDE];

    const int m0 = blockIdx.x * BM;
    const int j0 = blockIdx.y * BN;

    float acc[2][4][4] = {};
    mma_mainloop((const uint4*)g_xf, (const uint4*)g_bqkv,
                 m0 >> 4, j0 >> 3, acc, As, Bs);

    float* dst; int coff; float sc;
    if (j0 < 256)      { dst = g_q; coff = j0;       sc = SCALE; }
    else if (j0 < 512) { dst = g_k; coff = j0 - 256; sc = 1.0f;  }
    else               { dst = g_v; coff = j0 - 512; sc = 1.0f;  }

    const int lane = threadIdx.x & 31;
    const int warp = threadIdx.x >> 5;
    const int g  = lane >> 2;
    const int t4 = lane & 3;

    #pragma unroll
    for (int i = 0; i < 2; i++) {
        #pragma unroll
        for (int j = 0; j < 4; j++) {
            const int row = m0 + (warp & 3) * 32 + i * 16 + g;
            const int col = coff + (warp >> 2) * 32 + j * 8 + t4 * 2;
            *(float2*)&dst[(size_t)row * C_ + col] =
                make_float2(acc[i][j][0] * sc, acc[i][j][1] * sc);
            *(float2*)&dst[(size_t)(row + 8) * C_ + col] =
                make_float2(acc[i][j][2] * sc, acc[i][j][3] * sc);
        }
    }
}

// ======================================================================
// GEMM 2: projection.  out[n, j] = sum_k ao[n,k] * w_proj[j,k] + b[j]
// ======================================================================
__global__ void __launch_bounds__(256) gemm_proj(
    const float* __restrict__ bias, float* __restrict__ out)
{
    __shared__ unsigned As[2 * A_STRIDE];
    __shared__ unsigned Bs[2 * B_STRIDE];

    const int m0 = blockIdx.x * BM;
    const int j0 = blockIdx.y * BN;

    float acc[2][4][4] = {};
    mma_mainloop((const uint4*)g_aof, (const uint4*)g_bproj,
                 m0 >> 4, j0 >> 3, acc, As, Bs);

    const int lane = threadIdx.x & 31;
    const int warp = threadIdx.x >> 5;
    const int g  = lane >> 2;
    const int t4 = lane & 3;

    #pragma unroll
    for (int i = 0; i < 2; i++) {
        #pragma unroll
        for (int j = 0; j < 4; j++) {
            const int row = m0 + (warp & 3) * 32 + i * 16 + g;
            const int col = j0 + (warp >> 2) * 32 + j * 8 + t4 * 2;
            const float2 bv = *(const float2*)&bias[col];
            *(float2*)&out[(size_t)row * C_ + col] =
                make_float2(acc[i][j][0] + bv.x, acc[i][j][1] + bv.y);
            *(float2*)&out[(size_t)(row + 8) * C_ + col] =
                make_float2(acc[i][j][2] + bv.x, acc[i][j][3] + bv.y);
        }
    }
}

// ======================================================================
// Attention (tiled) — unchanged from R15.
// ======================================================================
#define TR 8
#define TC 4
#define HR 14
#define HC 10
#define KSTR 36

__global__ void __launch_bounds__(256) attn_tile(float* __restrict__ attn_ext, int ext)
{
    __shared__ __align__(16) float ks[HR*HC*KSTR];
    __shared__ __align__(16) float vs[HR*HC*32];
    __shared__ __align__(16) float qs[TR*TC*32];

    const int c0 = blockIdx.x * TC;
    const int r0 = blockIdx.y * TR;
    const int bh = blockIdx.z;
    const int h  = bh & 7;
    const int b  = bh >> 3;

    const int rb = max(r0 - 3, 0);
    const int rn = min(r0 + TR + 2, H_ - 1) - rb + 1;
    const int cb = max(c0 - 3, 0);
    const int cn = min(c0 + TC + 2, W_ - 1) - cb + 1;

    const int warp = threadIdx.x >> 5;
    const int lane = threadIdx.x & 31;

    float* ap = ext ? attn_ext : g_attn_dummy;

    const int area = rn * cn;
    for (int p = warp; p < area; p += 8) {
        const int plr = p / cn;
        const int plc = p - plr * cn;
        const int pix = (b * H_ + rb + plr) * W_ + cb + plc;
        const size_t ga = (size_t)pix * C_ + h * HD_ + lane;
        const int sp = plr * HC + plc;
        ks[sp * KSTR + lane] = g_k[ga];
        vs[sp * 32   + lane] = g_v[ga];
    }
    {
        const int i = r0 + warp;
        #pragma unroll
        for (int jj = 0; jj < TC; jj++) {
            const int pix = (b * H_ + i) * W_ + c0 + jj;
            qs[(warp * TC + jj) * 32 + lane] = g_q[(size_t)pix * C_ + h * HD_ + lane];
        }
    }
    __syncthreads();

    const int i   = r0 + warp;
    const int shl = min(max(i - 3, 0), H_ - KW_) - rb;
    const int o0 = (shl + lane / 7) * HC + lane % 7;
    const int t1 = (lane < 17) ? lane + 32 : 32;
    const int o1 = (shl + t1 / 7) * HC + t1 % 7;

    for (int jj = 0; jj < TC; jj++) {
        const int j   = c0 + jj;
        const int swl = min(max(j - 3, 0), W_ - KW_) - cb;
        const int pix = (b * H_ + i) * W_ + j;
        const int p0  = o0 + swl;
        const int p1  = o1 + swl;

        const float4* qrow = (const float4*)&qs[(warp * TC + jj) * 32];
        const float4* k0p  = (const float4*)&ks[p0 * KSTR];
        const float4* k1p  = (const float4*)&ks[p1 * KSTR];
        float l0 = 0.0f, l1 = 0.0f;
        #pragma unroll
        for (int dq = 0; dq < 8; dq++) {
            const float4 qd = qrow[dq];
            const float4 k0 = k0p[dq];
            const float4 k1 = k1p[dq];
            l0 = fmaf(qd.x, k0.x, fmaf(qd.y, k0.y, fmaf(qd.z, k0.z, fmaf(qd.w, k0.w, l0))));
            l1 = fmaf(qd.x, k1.x, fmaf(qd.y, k1.y, fmaf(qd.z, k1.z, fmaf(qd.w, k1.w, l1))));
        }
        if (lane >= 17) l1 = -1e30f;

        float m = fmaxf(l0, l1);
        #pragma unroll
        for (int o = 16; o > 0; o >>= 1)
            m = fmaxf(m, __shfl_xor_sync(0xffffffffu, m, o));
        const float e0 = __expf(l0 - m);
        const float e1 = (lane < 17) ? __expf(l1 - m) : 0.0f;
        float s = e0 + e1;
        #pragma unroll
        for (int o = 16; o > 0; o >>= 1)
            s += __shfl_xor_sync(0xffffffffu, s, o);
        const float inv = 1.0f / s;

        const size_t abase = (size_t)(((b * NH_ + h) * H_ + i) * W_ + j) * 49;
        ap[abase + lane] = e0 * inv;
        if (lane < 17) ap[abase + 32 + lane] = e1 * inv;

        const int pb = shl * HC + swl;
        float acc = 0.0f;
        #pragma unroll
        for (int t = 0; t < 49; t++) {
            const float a = (t < 32) ? __shfl_sync(0xffffffffu, e0, t)
                                     : __shfl_sync(0xffffffffu, e1, t - 32);
            acc = fmaf(a, vs[(pb + (t / 7) * HC + (t % 7)) * 32 + lane], acc);
        }
        g_ao[(size_t)pix * C_ + h * HD_ + lane] = acc * inv;
    }
}

// ======================================================================
extern "C" void kernel_launch(void* const* d_in, const int* in_sizes, int n_in,
                              void* d_out, int out_size)
{
    const float* x      = (const float*)d_in[0];
    const float* w_qk   = (const float*)d_in[1];
    const float* w_v    = (const float*)d_in[2];
    const float* w_proj = (const float*)d_in[3];
    const float* b_proj = (const float*)d_in[4];
    float* out = (float*)d_out;

    const int ext = (out_size >= OUT_ELEMS + ATTN_ELEMS) ? 1 : 0;
    float* attn_ptr = out + OUT_ELEMS;   // used only when ext==1

    unsigned* xf;  cudaGetSymbolAddress((void**)&xf,  g_xf);
    unsigned* aof; cudaGetSymbolAddress((void**)&aof, g_aof);
    unsigned* bq;  cudaGetSymbolAddress((void**)&bq,  g_bqkv);
    unsigned* bp;  cudaGetSymbolAddress((void**)&bp,  g_bproj);
    float* ao;     cudaGetSymbolAddress((void**)&ao,  g_ao);

    prep_afrag<<<NPIX / 16, 256>>>(x, xf);
    prep_ball <<<64, 256>>>(w_qk, w_v, w_proj, bq, bp);

    gemm_qkv <<<dim3(NPIX / BM, 768 / BN), 256>>>();
    attn_tile<<<dim3(W_ / TC, H_ / TR, B_ * NH_), 256>>>(attn_ptr, ext);

    prep_afrag<<<NPIX / 16, 256>>>(ao, aof);
    gemm_proj<<<dim3(NPIX / BM, C_ / BN), 256>>>(b_proj, out);
}